// round 1
// baseline (speedup 1.0000x reference)
#include <cuda_runtime.h>
#include <cuda_bf16.h>

// ---------------------------------------------------------------------------
// RelationLayer: L=128, B=16, E=512, C=64, KERNELS={1,3,5,7}, M=256, OUT=256
//
// Pipeline:
//  1) repack conv weights -> Wcat (512 x 1024), cols = (tap_global p)*64 + c
//  2) G = x(2048x512) @ Wcat            (tiled f32x2 GEMM)
//  3) f[l,b,m] = lrelu(cb + sum_t G[l-pad+t, b, p(t), c])   (gather)
//  4) uv = f(2048x256) @ Wuv(256x128)   (u = cols 0..63, v = cols 64..127)
//  5) pair kernel: per (j,b): for i: h1=lrelu(u_j+v_i+b0); 3x 64x64 MLP with
//     lrelu (f32x2 in registers, weights transposed in smem); sum over i -> s
//  6) head: t = lrelu(s@lw0.T+lb0); out = lrelu(t@lw1.T+lb1)
// ---------------------------------------------------------------------------

#define LL 128
#define BB 16
#define EE 512
#define CC 64
#define MM 256
#define ROWS 2048           // L*B
#define GCOLS 1024          // 16 taps * 64

// scratch (static device memory; no allocation at runtime)
__device__ float g_G[ROWS * GCOLS];     // 8 MB
__device__ float g_Wr[EE * GCOLS];      // 2 MB
__device__ float g_f[ROWS * MM];        // 2 MB
__device__ float g_Wuv[MM * 128];       // 128 KB
__device__ float g_uv[ROWS * 128];      // 1 MB
__device__ float g_s[ROWS * CC];        // 512 KB
__device__ float g_t[ROWS * CC];        // 512 KB
__device__ float g_hw0[CC * CC];        // lw0 transposed (64x64)
__device__ float g_hw1[CC * 256];       // lw1 transposed (64x256)

// ---------------- helpers ----------------
__device__ __forceinline__ float lrelu(float x) { return fmaxf(x, 0.1f * x); }

__device__ __forceinline__ unsigned long long pack_dup(float a) {
    unsigned long long r;
    asm("mov.b64 %0, {%1, %1};" : "=l"(r) : "f"(a));
    return r;
}
__device__ __forceinline__ void ffma2(unsigned long long& d,
                                      unsigned long long a,
                                      unsigned long long b) {
    asm("fma.rn.f32x2 %0, %1, %2, %0;" : "+l"(d) : "l"(a), "l"(b));
}
__device__ __forceinline__ void unpack2(unsigned long long v, float& a, float& b) {
    asm("mov.b64 {%0, %1}, %2;" : "=f"(a), "=f"(b) : "l"(v));
}

// ---------------- weight repack kernels ----------------
__global__ void repack_wr_kernel(const float* __restrict__ cw0,
                                 const float* __restrict__ cw1,
                                 const float* __restrict__ cw2,
                                 const float* __restrict__ cw3) {
    int idx = blockIdx.x * 256 + threadIdx.x;
    if (idx >= EE * GCOLS) return;
    int e = idx >> 10;
    int col = idx & 1023;
    int p = col >> 6;
    int c = col & 63;
    const float* w; int k, t;
    if (p < 1)      { w = cw0; k = 1; t = p; }
    else if (p < 4) { w = cw1; k = 3; t = p - 1; }
    else if (p < 9) { w = cw2; k = 5; t = p - 4; }
    else            { w = cw3; k = 7; t = p - 9; }
    g_Wr[idx] = w[(c * k + t) * EE + e];
}

// out[k*N + n] = in[n*K + k]   (in is N x K row-major)
__global__ void transpose_kernel(const float* __restrict__ in,
                                 float* __restrict__ out, int N, int K) {
    int idx = blockIdx.x * 256 + threadIdx.x;
    if (idx >= N * K) return;
    int k = idx / N;
    int n = idx - k * N;
    out[idx] = in[n * K + k];
}

__global__ void pack_wuv_kernel(const float* __restrict__ mw0) {
    int idx = blockIdx.x * 256 + threadIdx.x;
    if (idx >= MM * 128) return;
    int k = idx >> 7;
    int n = idx & 127;
    float v;
    if (n < 64) v = mw0[n * 512 + k];
    else        v = mw0[(n - 64) * 512 + 256 + k];
    g_Wuv[idx] = v;
}

// ---------------- generic tiled GEMM: C(MxN) = A(MxK) @ B(KxN) -------------
// 64x64 block tile, K step 16, 256 threads, 4x4 micro-tile using f32x2.
// M % 64 == 0, N % 64 == 0, K % 16 == 0. Optional bias + leaky relu epilogue.
__global__ void __launch_bounds__(256)
gemm64_kernel(const float* __restrict__ A, const float* __restrict__ B,
              float* __restrict__ C, int M, int N, int K,
              const float* __restrict__ bias, int act) {
    __shared__ float As[16][68];
    __shared__ float Bs[16][64];
    int tid = threadIdx.x;
    int tx = tid & 15, ty = tid >> 4;
    int m0 = blockIdx.y * 64, n0 = blockIdx.x * 64;

    int arow = tid >> 2;          // 0..63
    int akk = (tid & 3) * 4;      // 0,4,8,12
    int brow = tid >> 4;          // 0..15
    int bcol = (tid & 15) * 4;

    unsigned long long acc[4][2];
#pragma unroll
    for (int r = 0; r < 4; r++) { acc[r][0] = 0ull; acc[r][1] = 0ull; }

    const float* Aptr = A + (m0 + arow) * K + akk;
    const float* Bbase = B + brow * N + n0 + bcol;

    for (int k0 = 0; k0 < K; k0 += 16) {
        float4 a4 = *(const float4*)(Aptr);
        Aptr += 16;
        float4 b4 = *(const float4*)(Bbase + k0 * N);
        __syncthreads();
        As[akk + 0][arow] = a4.x;
        As[akk + 1][arow] = a4.y;
        As[akk + 2][arow] = a4.z;
        As[akk + 3][arow] = a4.w;
        *(float4*)&Bs[brow][bcol] = b4;
        __syncthreads();
#pragma unroll
        for (int kk = 0; kk < 16; kk++) {
            float4 av = *(const float4*)&As[kk][ty * 4];
            ulonglong2 bv = *(const ulonglong2*)&Bs[kk][tx * 4];
            unsigned long long a0 = pack_dup(av.x);
            unsigned long long a1 = pack_dup(av.y);
            unsigned long long a2 = pack_dup(av.z);
            unsigned long long a3 = pack_dup(av.w);
            ffma2(acc[0][0], a0, bv.x); ffma2(acc[0][1], a0, bv.y);
            ffma2(acc[1][0], a1, bv.x); ffma2(acc[1][1], a1, bv.y);
            ffma2(acc[2][0], a2, bv.x); ffma2(acc[2][1], a2, bv.y);
            ffma2(acc[3][0], a3, bv.x); ffma2(acc[3][1], a3, bv.y);
        }
    }

    int col = n0 + tx * 4;
    float4 bq = make_float4(0.f, 0.f, 0.f, 0.f);
    if (bias) bq = *(const float4*)(bias + col);
#pragma unroll
    for (int r = 0; r < 4; r++) {
        float c0, c1, c2, c3;
        unpack2(acc[r][0], c0, c1);
        unpack2(acc[r][1], c2, c3);
        c0 += bq.x; c1 += bq.y; c2 += bq.z; c3 += bq.w;
        if (act) { c0 = lrelu(c0); c1 = lrelu(c1); c2 = lrelu(c2); c3 = lrelu(c3); }
        float4 o = make_float4(c0, c1, c2, c3);
        *(float4*)(C + (m0 + ty * 4 + r) * N + col) = o;
    }
}

// ---------------- gather: G -> f (conv tap sum + bias + lrelu) -------------
__global__ void gather_f_kernel(const float* __restrict__ cb0,
                                const float* __restrict__ cb1,
                                const float* __restrict__ cb2,
                                const float* __restrict__ cb3) {
    int l = blockIdx.x;
    int b = blockIdx.y;
    int m = threadIdx.x;             // 0..255
    int br = m >> 6;
    int c = m & 63;
    int k, pad, base;
    const float* cb;
    if (br == 0)      { k = 1; base = 0; cb = cb0; }
    else if (br == 1) { k = 3; base = 1; cb = cb1; }
    else if (br == 2) { k = 5; base = 4; cb = cb2; }
    else              { k = 7; base = 9; cb = cb3; }
    pad = (k - 1) >> 1;
    float sum = cb[c];
    for (int t = 0; t < k; t++) {
        int l2 = l - pad + t;
        if ((unsigned)l2 < (unsigned)LL)
            sum += g_G[(l2 * BB + b) * GCOLS + (base + t) * 64 + c];
    }
    g_f[(l * BB + b) * MM + m] = lrelu(sum);
}

// ---------------- pair kernel -----------------------------------------------
// Block = (j_tile of 8, b). 128 threads, thread t handles i = t.
// Shared layout (floats):
//   WT1 @ 0, WT2 @ 4352, WT3 @ 8704   (each 64 x 68, transposed: WT[in][c])
//   V   @ 13056  (64 x 128: V[c][i])
//   U   @ 21248  (8 x 64)
//   BZ  @ 21760  (4 x 64: b0,b1,b2,b3)
//   RED @ 22016  (4 x 64)
// total = 22272 floats = 89088 bytes
#define SM_WT(w)   ((w) * 4352)
#define SM_V       13056
#define SM_U       21248
#define SM_B       21760
#define SM_RED     22016
#define SM_BYTES   (22272 * 4)

extern __shared__ float sm_pair[];

__device__ __forceinline__ void mlp_layer(float h[64], int woff, int boff) {
    unsigned long long acc[32];
    const unsigned long long* bp = (const unsigned long long*)&sm_pair[boff];
#pragma unroll
    for (int q = 0; q < 32; q++) acc[q] = bp[q];
#pragma unroll
    for (int in = 0; in < 64; in++) {
        unsigned long long h2 = pack_dup(h[in]);
        const float* wr = &sm_pair[woff + in * 68];
#pragma unroll
        for (int q8 = 0; q8 < 16; q8++) {
            ulonglong2 w2 = *(const ulonglong2*)(wr + q8 * 4);
            ffma2(acc[2 * q8 + 0], h2, w2.x);
            ffma2(acc[2 * q8 + 1], h2, w2.y);
        }
    }
#pragma unroll
    for (int q = 0; q < 32; q++) {
        float a, b;
        unpack2(acc[q], a, b);
        h[2 * q + 0] = lrelu(a);
        h[2 * q + 1] = lrelu(b);
    }
}

__global__ void __launch_bounds__(128, 2)
pair_kernel(const float* __restrict__ uv,
            const float* __restrict__ mw1, const float* __restrict__ mw2,
            const float* __restrict__ mw3,
            const float* __restrict__ mb0, const float* __restrict__ mb1,
            const float* __restrict__ mb2, const float* __restrict__ mb3,
            float* __restrict__ s_out) {
    int tid = threadIdx.x;
    int b = blockIdx.y;
    int j0 = blockIdx.x * 8;

    // stage transposed weights
    {
        const float* ws0 = mw1;
        const float* ws1 = mw2;
        const float* ws2 = mw3;
#pragma unroll
        for (int q = 0; q < 32; q++) {
            int idx = tid + 128 * q;
            int c = idx >> 6, in = idx & 63;
            sm_pair[SM_WT(0) + in * 68 + c] = ws0[idx];
            sm_pair[SM_WT(1) + in * 68 + c] = ws1[idx];
            sm_pair[SM_WT(2) + in * 68 + c] = ws2[idx];
        }
    }
    if (tid < 64) {
        sm_pair[SM_B + tid]       = mb0[tid];
        sm_pair[SM_B + 64 + tid]  = mb1[tid];
        sm_pair[SM_B + 128 + tid] = mb2[tid];
        sm_pair[SM_B + 192 + tid] = mb3[tid];
#pragma unroll
        for (int jt = 0; jt < 8; jt++)
            sm_pair[SM_U + jt * 64 + tid] = uv[((j0 + jt) * BB + b) * 128 + tid];
    }
    // stage V transposed: V[c][i]
    {
        const float* vp = uv + (tid * BB + b) * 128 + 64;
#pragma unroll
        for (int q = 0; q < 16; q++) {
            float4 v4 = *(const float4*)(vp + q * 4);
            sm_pair[SM_V + (q * 4 + 0) * 128 + tid] = v4.x;
            sm_pair[SM_V + (q * 4 + 1) * 128 + tid] = v4.y;
            sm_pair[SM_V + (q * 4 + 2) * 128 + tid] = v4.z;
            sm_pair[SM_V + (q * 4 + 3) * 128 + tid] = v4.w;
        }
    }
    __syncthreads();

    for (int jt = 0; jt < 8; jt++) {
        float h[64];
#pragma unroll
        for (int c = 0; c < 64; c++) {
            float x = sm_pair[SM_U + jt * 64 + c] +
                      sm_pair[SM_V + c * 128 + tid] +
                      sm_pair[SM_B + c];
            h[c] = lrelu(x);
        }
        mlp_layer(h, SM_WT(0), SM_B + 64);
        mlp_layer(h, SM_WT(1), SM_B + 128);
        mlp_layer(h, SM_WT(2), SM_B + 192);

        // warp butterfly reduce over i within warp (all 64 channels)
#pragma unroll
        for (int c = 0; c < 64; c++) {
            float v = h[c];
            v += __shfl_xor_sync(0xffffffffu, v, 16);
            v += __shfl_xor_sync(0xffffffffu, v, 8);
            v += __shfl_xor_sync(0xffffffffu, v, 4);
            v += __shfl_xor_sync(0xffffffffu, v, 2);
            v += __shfl_xor_sync(0xffffffffu, v, 1);
            h[c] = v;
        }
        int w = tid >> 5, l = tid & 31;
        sm_pair[SM_RED + w * 64 + l]      = h[l];
        sm_pair[SM_RED + w * 64 + 32 + l] = h[32 + l];
        __syncthreads();
        if (tid < 64) {
            float s = sm_pair[SM_RED + tid] + sm_pair[SM_RED + 64 + tid] +
                      sm_pair[SM_RED + 128 + tid] + sm_pair[SM_RED + 192 + tid];
            s_out[((j0 + jt) * BB + b) * CC + tid] = s;
        }
        __syncthreads();
    }
}

// ---------------- host launch ----------------
extern "C" void kernel_launch(void* const* d_in, const int* in_sizes, int n_in,
                              void* d_out, int out_size) {
    const float* x   = (const float*)d_in[0];
    const float* cw0 = (const float*)d_in[1];
    const float* cb0 = (const float*)d_in[2];
    const float* cw1 = (const float*)d_in[3];
    const float* cb1 = (const float*)d_in[4];
    const float* cw2 = (const float*)d_in[5];
    const float* cb2 = (const float*)d_in[6];
    const float* cw3 = (const float*)d_in[7];
    const float* cb3 = (const float*)d_in[8];
    const float* mw0 = (const float*)d_in[9];
    const float* mb0 = (const float*)d_in[10];
    const float* mw1 = (const float*)d_in[11];
    const float* mb1 = (const float*)d_in[12];
    const float* mw2 = (const float*)d_in[13];
    const float* mb2 = (const float*)d_in[14];
    const float* mw3 = (const float*)d_in[15];
    const float* mb3 = (const float*)d_in[16];
    const float* lw0 = (const float*)d_in[17];
    const float* lb0 = (const float*)d_in[18];
    const float* lw1 = (const float*)d_in[19];
    const float* lb1 = (const float*)d_in[20];
    float* out = (float*)d_out;

    float *G, *Wr, *f, *Wuv, *uvb, *sbuf, *tbuf, *hw0, *hw1;
    cudaGetSymbolAddress((void**)&G, g_G);
    cudaGetSymbolAddress((void**)&Wr, g_Wr);
    cudaGetSymbolAddress((void**)&f, g_f);
    cudaGetSymbolAddress((void**)&Wuv, g_Wuv);
    cudaGetSymbolAddress((void**)&uvb, g_uv);
    cudaGetSymbolAddress((void**)&sbuf, g_s);
    cudaGetSymbolAddress((void**)&tbuf, g_t);
    cudaGetSymbolAddress((void**)&hw0, g_hw0);
    cudaGetSymbolAddress((void**)&hw1, g_hw1);

    // weight repacks (cheap)
    repack_wr_kernel<<<(EE * GCOLS + 255) / 256, 256>>>(cw0, cw1, cw2, cw3);
    transpose_kernel<<<(64 * 64 + 255) / 256, 256>>>(lw0, hw0, 64, 64);
    transpose_kernel<<<(256 * 64 + 255) / 256, 256>>>(lw1, hw1, 256, 64);
    pack_wuv_kernel<<<(MM * 128 + 255) / 256, 256>>>(mw0);

    // conv as GEMM: G(2048x1024) = x(2048x512) @ Wr(512x1024)
    gemm64_kernel<<<dim3(GCOLS / 64, ROWS / 64), 256>>>(
        x, Wr, G, ROWS, GCOLS, EE, nullptr, 0);

    // gather taps -> f
    gather_f_kernel<<<dim3(LL, BB), 256>>>(cb0, cb1, cb2, cb3);

    // uv(2048x128) = f(2048x256) @ Wuv(256x128)
    gemm64_kernel<<<dim3(2, ROWS / 64), 256>>>(
        f, Wuv, uvb, ROWS, 128, MM, nullptr, 0);

    // pairwise MLP chain + reduction over i
    cudaFuncSetAttribute(pair_kernel,
                         cudaFuncAttributeMaxDynamicSharedMemorySize, SM_BYTES);
    pair_kernel<<<dim3(16, 16), 128, SM_BYTES>>>(
        uvb, mw1, mw2, mw3, mb0, mb1, mb2, mb3, sbuf);

    // head
    gemm64_kernel<<<dim3(1, ROWS / 64), 256>>>(
        sbuf, hw0, tbuf, ROWS, 64, 64, lb0, 1);
    gemm64_kernel<<<dim3(4, ROWS / 64), 256>>>(
        tbuf, hw1, out, ROWS, 256, 64, lb1, 1);
}

// round 3
// speedup vs baseline: 2.2171x; 2.2171x over previous
#include <cuda_runtime.h>
#include <cuda_bf16.h>
#include <cstdint>

// ---------------------------------------------------------------------------
// RelationLayer: L=128, B=16, E=512, C=64, KERNELS={1,3,5,7}, M=256, OUT=256
//  1) repack conv weights -> Wr (512 x 1024)
//  2) G = x(2048x512) @ Wr                 (FFMA2 GEMM)
//  3) f = lrelu(gather taps + bias)
//  4) uv = f(2048x256) @ Wuv(256x128)      (FFMA2 GEMM)
//  5) pair kernel: mma.sync m16n8k16 bf16 hi/lo split, in-register layer
//     chaining, i-reduction, fused head.
// ---------------------------------------------------------------------------

#define LL 128
#define BB 16
#define EE 512
#define MM 256
#define ROWS 2048
#define GCOLS 1024

__device__ float g_G[ROWS * GCOLS];
__device__ float g_Wr[EE * GCOLS];
__device__ float g_f[ROWS * MM];
__device__ float g_Wuv[MM * 128];
__device__ float g_uv[ROWS * 128];

// ===================== helpers ==============================================
__device__ __forceinline__ float lrelu(float x) { return fmaxf(x, 0.1f * x); }

__device__ __forceinline__ unsigned long long pack_dup(float a) {
    unsigned long long r;
    asm("mov.b64 %0, {%1, %1};" : "=l"(r) : "f"(a));
    return r;
}
__device__ __forceinline__ void ffma2(unsigned long long& d,
                                      unsigned long long a,
                                      unsigned long long b) {
    asm("fma.rn.f32x2 %0, %1, %2, %0;" : "+l"(d) : "l"(a), "l"(b));
}
__device__ __forceinline__ void unpack2(unsigned long long v, float& a, float& b) {
    asm("mov.b64 {%0, %1}, %2;" : "=f"(a), "=f"(b) : "l"(v));
}

// split two f32 into bf16-hi word and bf16-lo (residual) word
// low 16 bits = first element (smaller index)
__device__ __forceinline__ void split2(float x0, float x1,
                                       uint32_t& hiw, uint32_t& low) {
    __nv_bfloat16 h0 = __float2bfloat16(x0);
    __nv_bfloat16 h1 = __float2bfloat16(x1);
    float r0 = x0 - __bfloat162float(h0);
    float r1 = x1 - __bfloat162float(h1);
    __nv_bfloat16 l0 = __float2bfloat16(r0);
    __nv_bfloat16 l1 = __float2bfloat16(r1);
    __nv_bfloat162 hp; hp.x = h0; hp.y = h1;
    __nv_bfloat162 lp; lp.x = l0; lp.y = l1;
    hiw = *(uint32_t*)&hp;
    low = *(uint32_t*)&lp;
}

// mma.sync m16n8k16 bf16 -> f32 accumulate (baseline PTX, no 'a' feature)
__device__ __forceinline__ void mma16816(float c[4], const uint32_t a[4],
                                         uint32_t b0, uint32_t b1) {
    asm volatile(
        "mma.sync.aligned.m16n8k16.row.col.f32.bf16.bf16.f32 "
        "{%0,%1,%2,%3}, {%4,%5,%6,%7}, {%8,%9}, {%0,%1,%2,%3};"
        : "+f"(c[0]), "+f"(c[1]), "+f"(c[2]), "+f"(c[3])
        : "r"(a[0]), "r"(a[1]), "r"(a[2]), "r"(a[3]), "r"(b0), "r"(b1));
}

// ===================== repack kernels =======================================
__global__ void repack_wr_kernel(const float* __restrict__ cw0,
                                 const float* __restrict__ cw1,
                                 const float* __restrict__ cw2,
                                 const float* __restrict__ cw3) {
    int idx = blockIdx.x * 256 + threadIdx.x;
    if (idx >= EE * GCOLS) return;
    int e = idx >> 10;
    int col = idx & 1023;
    int p = col >> 6;
    int c = col & 63;
    const float* w; int k, t;
    if (p < 1)      { w = cw0; k = 1; t = p; }
    else if (p < 4) { w = cw1; k = 3; t = p - 1; }
    else if (p < 9) { w = cw2; k = 5; t = p - 4; }
    else            { w = cw3; k = 7; t = p - 9; }
    g_Wr[idx] = w[(c * k + t) * EE + e];
}

__global__ void pack_wuv_kernel(const float* __restrict__ mw0) {
    int idx = blockIdx.x * 256 + threadIdx.x;
    if (idx >= MM * 128) return;
    int k = idx >> 7;
    int n = idx & 127;
    float v;
    if (n < 64) v = mw0[n * 512 + k];
    else        v = mw0[(n - 64) * 512 + 256 + k];
    g_Wuv[idx] = v;
}

// ===================== FFMA2 tiled GEMM (proven) ============================
__global__ void __launch_bounds__(256)
gemm64_kernel(const float* __restrict__ A, const float* __restrict__ B,
              float* __restrict__ C, int M, int N, int K,
              const float* __restrict__ bias, int act) {
    __shared__ float As[16][68];
    __shared__ float Bs[16][64];
    int tid = threadIdx.x;
    int tx = tid & 15, ty = tid >> 4;
    int m0 = blockIdx.y * 64, n0 = blockIdx.x * 64;

    int arow = tid >> 2;
    int akk = (tid & 3) * 4;
    int brow = tid >> 4;
    int bcol = (tid & 15) * 4;

    unsigned long long acc[4][2];
#pragma unroll
    for (int r = 0; r < 4; r++) { acc[r][0] = 0ull; acc[r][1] = 0ull; }

    const float* Aptr = A + (m0 + arow) * K + akk;
    const float* Bbase = B + brow * N + n0 + bcol;

    for (int k0 = 0; k0 < K; k0 += 16) {
        float4 a4 = *(const float4*)(Aptr);
        Aptr += 16;
        float4 b4 = *(const float4*)(Bbase + k0 * N);
        __syncthreads();
        As[akk + 0][arow] = a4.x;
        As[akk + 1][arow] = a4.y;
        As[akk + 2][arow] = a4.z;
        As[akk + 3][arow] = a4.w;
        *(float4*)&Bs[brow][bcol] = b4;
        __syncthreads();
#pragma unroll
        for (int kk = 0; kk < 16; kk++) {
            float4 av = *(const float4*)&As[kk][ty * 4];
            ulonglong2 bv = *(const ulonglong2*)&Bs[kk][tx * 4];
            unsigned long long a0 = pack_dup(av.x);
            unsigned long long a1 = pack_dup(av.y);
            unsigned long long a2 = pack_dup(av.z);
            unsigned long long a3 = pack_dup(av.w);
            ffma2(acc[0][0], a0, bv.x); ffma2(acc[0][1], a0, bv.y);
            ffma2(acc[1][0], a1, bv.x); ffma2(acc[1][1], a1, bv.y);
            ffma2(acc[2][0], a2, bv.x); ffma2(acc[2][1], a2, bv.y);
            ffma2(acc[3][0], a3, bv.x); ffma2(acc[3][1], a3, bv.y);
        }
    }

    int col = n0 + tx * 4;
    float4 bq = make_float4(0.f, 0.f, 0.f, 0.f);
    if (bias) bq = *(const float4*)(bias + col);
#pragma unroll
    for (int r = 0; r < 4; r++) {
        float c0, c1, c2, c3;
        unpack2(acc[r][0], c0, c1);
        unpack2(acc[r][1], c2, c3);
        c0 += bq.x; c1 += bq.y; c2 += bq.z; c3 += bq.w;
        if (act) { c0 = lrelu(c0); c1 = lrelu(c1); c2 = lrelu(c2); c3 = lrelu(c3); }
        float4 o = make_float4(c0, c1, c2, c3);
        *(float4*)(C + (m0 + ty * 4 + r) * N + col) = o;
    }
}

// ===================== gather taps -> f =====================================
__global__ void gather_f_kernel(const float* __restrict__ cb0,
                                const float* __restrict__ cb1,
                                const float* __restrict__ cb2,
                                const float* __restrict__ cb3) {
    int l = blockIdx.x;
    int b = blockIdx.y;
    int m = threadIdx.x;
    int br = m >> 6;
    int c = m & 63;
    int k, pad, base;
    const float* cb;
    if (br == 0)      { k = 1; base = 0; cb = cb0; }
    else if (br == 1) { k = 3; base = 1; cb = cb1; }
    else if (br == 2) { k = 5; base = 4; cb = cb2; }
    else              { k = 7; base = 9; cb = cb3; }
    pad = (k - 1) >> 1;
    float sum = cb[c];
    for (int t = 0; t < k; t++) {
        int l2 = l - pad + t;
        if ((unsigned)l2 < (unsigned)LL)
            sum += g_G[(l2 * BB + b) * GCOLS + (base + t) * 64 + c];
    }
    g_f[(l * BB + b) * MM + m] = lrelu(sum);
}

// ===================== pair kernel (mma.sync) ===============================
// grid (16, 16): blockIdx.x -> j-tile of 8, blockIdx.y -> b. 128 threads.
// Warp w handles i-rows [w*32, w*32+32) as 2 m-tiles of 16.
//
// SMEM layout (bytes from dynamic base):
//   W tiles  @ 0     : per layer l: hi at l*18432, lo at l*18432+9216,
//                      each bf16 [64][72] (out-ch n rows, in-ch k cols)
//   V        @ 55296 : f32 [64][132]  V[k][i]
//   U        @ 89088 : f32 [8][64]
//   BIAS     @ 91136 : f32 [4][64]  (b0,b1,b2,b3)
//   RED      @ 92160 : f32 [4][64]
//   SR       @ 93184 : f32 [8][64]
//   TR       @ 95232 : f32 [512]
// total 97280 bytes
#define PW_STRIDE 72
#define PV_STRIDE 132
#define P_W(l)   ((l) * 18432)
#define P_WLO(l) ((l) * 18432 + 9216)
#define P_V    55296
#define P_U    89088
#define P_B    91136
#define P_RED  92160
#define P_SR   93184
#define P_TR   95232
#define PAIR_SMEM_BYTES 97280

__global__ void __launch_bounds__(128, 2)
pair_mma_kernel(const float* __restrict__ uv,
                const float* __restrict__ mw1, const float* __restrict__ mw2,
                const float* __restrict__ mw3,
                const float* __restrict__ mb0, const float* __restrict__ mb1,
                const float* __restrict__ mb2, const float* __restrict__ mb3,
                const float* __restrict__ lw0, const float* __restrict__ lb0,
                const float* __restrict__ lw1, const float* __restrict__ lb1,
                float* __restrict__ out) {
    extern __shared__ char smp[];
    int tid = threadIdx.x, w = tid >> 5, lane = tid & 31;
    int g = lane >> 2, t4 = lane & 3;
    int b = blockIdx.y, j0 = blockIdx.x * 8;

    // ---- stage weights hi/lo bf16 [n][k] stride 72 ----
    for (int l = 0; l < 3; l++) {
        const float* wsrc = (l == 0) ? mw1 : (l == 1) ? mw2 : mw3;
        __nv_bfloat16* whi = (__nv_bfloat16*)(smp + P_W(l));
        __nv_bfloat16* wlo = (__nv_bfloat16*)(smp + P_WLO(l));
        for (int idx = tid; idx < 4096; idx += 128) {
            int n = idx >> 6, k = idx & 63;
            float v = wsrc[idx];
            __nv_bfloat16 h = __float2bfloat16(v);
            __nv_bfloat16 lo = __float2bfloat16(v - __bfloat162float(h));
            whi[n * PW_STRIDE + k] = h;
            wlo[n * PW_STRIDE + k] = lo;
        }
    }
    // ---- stage V[k][i] (f32, stride 132) ----
    {
        float* V = (float*)(smp + P_V);
        const float* vp = uv + (tid * BB + b) * 128 + 64;
#pragma unroll
        for (int q = 0; q < 16; q++) {
            float4 v4 = *(const float4*)(vp + q * 4);
            V[(q * 4 + 0) * PV_STRIDE + tid] = v4.x;
            V[(q * 4 + 1) * PV_STRIDE + tid] = v4.y;
            V[(q * 4 + 2) * PV_STRIDE + tid] = v4.z;
            V[(q * 4 + 3) * PV_STRIDE + tid] = v4.w;
        }
    }
    if (tid < 64) {
        float* U = (float*)(smp + P_U);
#pragma unroll
        for (int jt = 0; jt < 8; jt++)
            U[jt * 64 + tid] = uv[((j0 + jt) * BB + b) * 128 + tid];
        float* Bs = (float*)(smp + P_B);
        Bs[tid] = mb0[tid];
        Bs[64 + tid] = mb1[tid];
        Bs[128 + tid] = mb2[tid];
        Bs[192 + tid] = mb3[tid];
    }
    __syncthreads();

    const float* V = (const float*)(smp + P_V);
    const float* U = (const float*)(smp + P_U);
    const float* BIAS = (const float*)(smp + P_B);
    float* RED = (float*)(smp + P_RED);
    float* SR = (float*)(smp + P_SR);

    for (int jt = 0; jt < 8; jt++) {
        uint32_t Ahi[2][4][4], Alo[2][4][4];

        // ---- layer-1 A fragments: x = lrelu(u + v + b0) ----
#pragma unroll
        for (int mt = 0; mt < 2; mt++) {
            int r0 = w * 32 + mt * 16 + g;
            int r1 = r0 + 8;
#pragma unroll
            for (int kc = 0; kc < 4; kc++) {
                int k0 = kc * 16 + 2 * t4;
                float ub0 = U[jt * 64 + k0]     + BIAS[k0];
                float ub1 = U[jt * 64 + k0 + 1] + BIAS[k0 + 1];
                float ub8 = U[jt * 64 + k0 + 8] + BIAS[k0 + 8];
                float ub9 = U[jt * 64 + k0 + 9] + BIAS[k0 + 9];
                float x00 = lrelu(ub0 + V[k0 * PV_STRIDE + r0]);
                float x01 = lrelu(ub1 + V[(k0 + 1) * PV_STRIDE + r0]);
                float x10 = lrelu(ub0 + V[k0 * PV_STRIDE + r1]);
                float x11 = lrelu(ub1 + V[(k0 + 1) * PV_STRIDE + r1]);
                float x08 = lrelu(ub8 + V[(k0 + 8) * PV_STRIDE + r0]);
                float x09 = lrelu(ub9 + V[(k0 + 9) * PV_STRIDE + r0]);
                float x18 = lrelu(ub8 + V[(k0 + 8) * PV_STRIDE + r1]);
                float x19 = lrelu(ub9 + V[(k0 + 9) * PV_STRIDE + r1]);
                split2(x00, x01, Ahi[mt][kc][0], Alo[mt][kc][0]);
                split2(x10, x11, Ahi[mt][kc][1], Alo[mt][kc][1]);
                split2(x08, x09, Ahi[mt][kc][2], Alo[mt][kc][2]);
                split2(x18, x19, Ahi[mt][kc][3], Alo[mt][kc][3]);
            }
        }

        // ---- 3 chained MMA layers ----
        float Cc[2][8][4];
#pragma unroll
        for (int l = 0; l < 3; l++) {
#pragma unroll
            for (int mt = 0; mt < 2; mt++)
#pragma unroll
                for (int nt = 0; nt < 8; nt++)
#pragma unroll
                    for (int q = 0; q < 4; q++) Cc[mt][nt][q] = 0.f;

            const __nv_bfloat16* whi = (const __nv_bfloat16*)(smp + P_W(l));
            const __nv_bfloat16* wlo = (const __nv_bfloat16*)(smp + P_WLO(l));
#pragma unroll
            for (int kc = 0; kc < 4; kc++) {
                int kk = kc * 16 + 2 * t4;
#pragma unroll
                for (int nt = 0; nt < 8; nt++) {
                    int nrow = nt * 8 + g;
                    uint32_t bh0 = *(const uint32_t*)&whi[nrow * PW_STRIDE + kk];
                    uint32_t bh1 = *(const uint32_t*)&whi[nrow * PW_STRIDE + kk + 8];
                    uint32_t bl0 = *(const uint32_t*)&wlo[nrow * PW_STRIDE + kk];
                    uint32_t bl1 = *(const uint32_t*)&wlo[nrow * PW_STRIDE + kk + 8];
                    mma16816(Cc[0][nt], Ahi[0][kc], bh0, bh1);
                    mma16816(Cc[1][nt], Ahi[1][kc], bh0, bh1);
                    mma16816(Cc[0][nt], Ahi[0][kc], bl0, bl1);
                    mma16816(Cc[1][nt], Ahi[1][kc], bl0, bl1);
                    mma16816(Cc[0][nt], Alo[0][kc], bh0, bh1);
                    mma16816(Cc[1][nt], Alo[1][kc], bh0, bh1);
                }
            }

            if (l < 2) {
                const float* bl = BIAS + 64 * (l + 1);
#pragma unroll
                for (int nt = 0; nt < 8; nt++) {
                    int col = nt * 8 + 2 * t4;
                    float bx = bl[col], by = bl[col + 1];
                    int kc2 = nt >> 1, ri = (nt & 1) * 2;
#pragma unroll
                    for (int mt = 0; mt < 2; mt++) {
                        float h0 = lrelu(Cc[mt][nt][0] + bx);
                        float h1 = lrelu(Cc[mt][nt][1] + by);
                        float h2 = lrelu(Cc[mt][nt][2] + bx);
                        float h3 = lrelu(Cc[mt][nt][3] + by);
                        split2(h0, h1, Ahi[mt][kc2][ri], Alo[mt][kc2][ri]);
                        split2(h2, h3, Ahi[mt][kc2][ri + 1], Alo[mt][kc2][ri + 1]);
                    }
                }
            }
        }

        // ---- final: bias + lrelu, reduce over i ----
        {
            const float* bl = BIAS + 192;
#pragma unroll
            for (int nt = 0; nt < 8; nt++) {
                int col = nt * 8 + 2 * t4;
                float bx = bl[col], by = bl[col + 1];
                float s0 = lrelu(Cc[0][nt][0] + bx) + lrelu(Cc[0][nt][2] + bx) +
                           lrelu(Cc[1][nt][0] + bx) + lrelu(Cc[1][nt][2] + bx);
                float s1 = lrelu(Cc[0][nt][1] + by) + lrelu(Cc[0][nt][3] + by) +
                           lrelu(Cc[1][nt][1] + by) + lrelu(Cc[1][nt][3] + by);
                s0 += __shfl_xor_sync(0xffffffffu, s0, 4);
                s0 += __shfl_xor_sync(0xffffffffu, s0, 8);
                s0 += __shfl_xor_sync(0xffffffffu, s0, 16);
                s1 += __shfl_xor_sync(0xffffffffu, s1, 4);
                s1 += __shfl_xor_sync(0xffffffffu, s1, 8);
                s1 += __shfl_xor_sync(0xffffffffu, s1, 16);
                if (lane < 4) {
                    RED[w * 64 + col] = s0;
                    RED[w * 64 + col + 1] = s1;
                }
            }
        }
        __syncthreads();
        if (tid < 64) {
            float s = RED[tid] + RED[64 + tid] + RED[128 + tid] + RED[192 + tid];
            SR[jt * 64 + tid] = s;
        }
        __syncthreads();
    }

    // ---- fused head: t = lrelu(s@lw0.T+lb0); out = lrelu(t@lw1.T+lb1) ----
    float* TR = (float*)(smp + P_TR);
#pragma unroll
    for (int q = 0; q < 4; q++) {
        int idx = tid + 128 * q;
        int jt = idx >> 6, o = idx & 63;
        const float* wr = lw0 + o * 64;
        float acc = lb0[o];
#pragma unroll
        for (int c = 0; c < 64; c += 4) {
            float4 w4 = *(const float4*)(wr + c);
            acc += SR[jt * 64 + c] * w4.x + SR[jt * 64 + c + 1] * w4.y +
                   SR[jt * 64 + c + 2] * w4.z + SR[jt * 64 + c + 3] * w4.w;
        }
        TR[idx] = lrelu(acc);
    }
    __syncthreads();
#pragma unroll
    for (int q = 0; q < 16; q++) {
        int idx = tid + 128 * q;
        int jt = idx >> 8, o = idx & 255;
        const float* wr = lw1 + o * 64;
        float acc = lb1[o];
#pragma unroll
        for (int c = 0; c < 64; c += 4) {
            float4 w4 = *(const float4*)(wr + c);
            acc += TR[jt * 64 + c] * w4.x + TR[jt * 64 + c + 1] * w4.y +
                   TR[jt * 64 + c + 2] * w4.z + TR[jt * 64 + c + 3] * w4.w;
        }
        out[((j0 + jt) * BB + b) * 256 + o] = lrelu(acc);
    }
}

// ===================== host launch ==========================================
extern "C" void kernel_launch(void* const* d_in, const int* in_sizes, int n_in,
                              void* d_out, int out_size) {
    const float* x   = (const float*)d_in[0];
    const float* cw0 = (const float*)d_in[1];
    const float* cb0 = (const float*)d_in[2];
    const float* cw1 = (const float*)d_in[3];
    const float* cb1 = (const float*)d_in[4];
    const float* cw2 = (const float*)d_in[5];
    const float* cb2 = (const float*)d_in[6];
    const float* cw3 = (const float*)d_in[7];
    const float* cb3 = (const float*)d_in[8];
    const float* mw0 = (const float*)d_in[9];
    const float* mb0 = (const float*)d_in[10];
    const float* mw1 = (const float*)d_in[11];
    const float* mb1 = (const float*)d_in[12];
    const float* mw2 = (const float*)d_in[13];
    const float* mb2 = (const float*)d_in[14];
    const float* mw3 = (const float*)d_in[15];
    const float* mb3 = (const float*)d_in[16];
    const float* lw0 = (const float*)d_in[17];
    const float* lb0 = (const float*)d_in[18];
    const float* lw1 = (const float*)d_in[19];
    const float* lb1 = (const float*)d_in[20];
    float* out = (float*)d_out;

    float *G, *Wr, *f, *Wuv, *uvb;
    cudaGetSymbolAddress((void**)&G, g_G);
    cudaGetSymbolAddress((void**)&Wr, g_Wr);
    cudaGetSymbolAddress((void**)&f, g_f);
    cudaGetSymbolAddress((void**)&Wuv, g_Wuv);
    cudaGetSymbolAddress((void**)&uvb, g_uv);

    repack_wr_kernel<<<(EE * GCOLS + 255) / 256, 256>>>(cw0, cw1, cw2, cw3);
    pack_wuv_kernel<<<(MM * 128 + 255) / 256, 256>>>(mw0);

    // conv as GEMM: G(2048x1024) = x(2048x512) @ Wr(512x1024)
    gemm64_kernel<<<dim3(GCOLS / 64, ROWS / 64), 256>>>(
        x, Wr, G, ROWS, GCOLS, EE, nullptr, 0);

    gather_f_kernel<<<dim3(LL, BB), 256>>>(cb0, cb1, cb2, cb3);

    // uv(2048x128) = f(2048x256) @ Wuv(256x128)
    gemm64_kernel<<<dim3(2, ROWS / 64), 256>>>(
        f, Wuv, uvb, ROWS, 128, MM, nullptr, 0);

    // pair stage + fused head (mma.sync bf16 split)
    cudaFuncSetAttribute(pair_mma_kernel,
                         cudaFuncAttributeMaxDynamicSharedMemorySize,
                         PAIR_SMEM_BYTES);
    pair_mma_kernel<<<dim3(16, 16), 128, PAIR_SMEM_BYTES>>>(
        uvb, mw1, mw2, mw3, mb0, mb1, mb2, mb3,
        lw0, lb0, lw1, lb1, out);
}

// round 5
// speedup vs baseline: 2.7902x; 1.2585x over previous
#include <cuda_runtime.h>
#include <cuda_bf16.h>
#include <cstdint>

// ---------------------------------------------------------------------------
// RelationLayer: L=128, B=16, E=512, C=64, KERNELS={1,3,5,7}, M=256, OUT=256
//  1) repack conv weights -> bf16 hi/lo planes Wr[n=1024][k=512]
//  2) G = x(2048x512) @ Wr               (tensor-core bf16-split GEMM)
//  3) f = lrelu(gather taps + bias)
//  4) uv = f(2048x256) @ Wuv(256x128)    (tensor-core bf16-split GEMM)
//  5) pair kernel: mma.sync m16n8k16 bf16 hi/lo split, in-register layer
//     chaining, i-reduction, fused head.
// ---------------------------------------------------------------------------

#define LL 128
#define BB 16
#define EE 512
#define MM 256
#define ROWS 2048
#define GCOLS 1024

__device__ float g_G[ROWS * GCOLS];
__device__ float g_f[ROWS * MM];
__device__ float g_uv[ROWS * 128];
__device__ __nv_bfloat16 g_Wrh[GCOLS * EE];
__device__ __nv_bfloat16 g_Wrl[GCOLS * EE];
__device__ __nv_bfloat16 g_Wuvh[128 * MM];
__device__ __nv_bfloat16 g_Wuvl[128 * MM];

// ===================== helpers ==============================================
__device__ __forceinline__ float lrelu(float x) { return fmaxf(x, 0.1f * x); }

// split two f32 into bf16-hi word and bf16-lo (residual) word
// low 16 bits = first element (smaller index)
__device__ __forceinline__ void split2(float x0, float x1,
                                       uint32_t& hiw, uint32_t& low) {
    __nv_bfloat16 h0 = __float2bfloat16(x0);
    __nv_bfloat16 h1 = __float2bfloat16(x1);
    float r0 = x0 - __bfloat162float(h0);
    float r1 = x1 - __bfloat162float(h1);
    __nv_bfloat16 l0 = __float2bfloat16(r0);
    __nv_bfloat16 l1 = __float2bfloat16(r1);
    __nv_bfloat162 hp; hp.x = h0; hp.y = h1;
    __nv_bfloat162 lp; lp.x = l0; lp.y = l1;
    hiw = *(uint32_t*)&hp;
    low = *(uint32_t*)&lp;
}

// mma.sync m16n8k16 bf16 -> f32 accumulate (baseline PTX, no 'a' feature)
__device__ __forceinline__ void mma16816(float c[4], const uint32_t a[4],
                                         uint32_t b0, uint32_t b1) {
    asm volatile(
        "mma.sync.aligned.m16n8k16.row.col.f32.bf16.bf16.f32 "
        "{%0,%1,%2,%3}, {%4,%5,%6,%7}, {%8,%9}, {%0,%1,%2,%3};"
        : "+f"(c[0]), "+f"(c[1]), "+f"(c[2]), "+f"(c[3])
        : "r"(a[0]), "r"(a[1]), "r"(a[2]), "r"(a[3]), "r"(b0), "r"(b1));
}

// ===================== repack kernels (to bf16 hi/lo [n][k]) ================
__global__ void repack_wr_kernel(const float* __restrict__ cw0,
                                 const float* __restrict__ cw1,
                                 const float* __restrict__ cw2,
                                 const float* __restrict__ cw3) {
    int idx = blockIdx.x * 256 + threadIdx.x;
    if (idx >= EE * GCOLS) return;
    int col = idx >> 9;            // n: 0..1023
    int e = idx & 511;             // k
    int p = col >> 6;
    int c = col & 63;
    const float* w; int k, t;
    if (p < 1)      { w = cw0; k = 1; t = p; }
    else if (p < 4) { w = cw1; k = 3; t = p - 1; }
    else if (p < 9) { w = cw2; k = 5; t = p - 4; }
    else            { w = cw3; k = 7; t = p - 9; }
    float v = w[(c * k + t) * EE + e];
    __nv_bfloat16 h = __float2bfloat16(v);
    g_Wrh[idx] = h;
    g_Wrl[idx] = __float2bfloat16(v - __bfloat162float(h));
}

__global__ void pack_wuv_kernel(const float* __restrict__ mw0) {
    int idx = blockIdx.x * 256 + threadIdx.x;
    if (idx >= 128 * MM) return;
    int n = idx >> 8;              // 0..127
    int k = idx & 255;
    float v;
    if (n < 64) v = mw0[n * 512 + k];
    else        v = mw0[(n - 64) * 512 + 256 + k];
    __nv_bfloat16 h = __float2bfloat16(v);
    g_Wuvh[idx] = h;
    g_Wuvl[idx] = __float2bfloat16(v - __bfloat162float(h));
}

// ===================== tensor-core bf16-split GEMM ==========================
// C(MxN) = A(MxK) @ B(KxN), A f32 row-major, B given as bf16 hi/lo [N][K].
// Block tile 128x128, K-step 64, 256 threads (8 warps, each 32m x 64n).
// M%128==0, N%128==0, K%64==0.
#define TS 72            // padded k-stride in bf16 units
#define SA_HI 0
#define SA_LO (128 * TS)
#define SB_HI (256 * TS)
#define SB_LO (384 * TS)
#define GEMM_SMEM_BYTES (512 * TS * 2)

__global__ void __launch_bounds__(256, 1)
gemm_tc_kernel(const float* __restrict__ A,
               const __nv_bfloat16* __restrict__ Bhi,
               const __nv_bfloat16* __restrict__ Blo,
               float* __restrict__ C, int M, int N, int K) {
    extern __shared__ __nv_bfloat16 sm[];
    int tid = threadIdx.x, w = tid >> 5, lane = tid & 31;
    int g = lane >> 2, t4 = lane & 3;
    int m0 = blockIdx.y * 128, n0 = blockIdx.x * 128;
    int mw = (w & 3) * 32;          // warp m offset within tile
    int nw = (w >> 2) * 64;         // warp n offset within tile

    // loader indices: each thread covers 32 consecutive k of one row
    int la_row = tid >> 1;                    // 0..127
    int la_col = (tid & 1) * 32;              // 0 or 32
    const float* Ap = A + (m0 + la_row) * K + la_col;
    const __nv_bfloat16* Bhp = Bhi + (n0 + la_row) * K + la_col;
    const __nv_bfloat16* Blp = Blo + (n0 + la_row) * K + la_col;

    float Cc[2][8][4];
#pragma unroll
    for (int mt = 0; mt < 2; mt++)
#pragma unroll
        for (int nt = 0; nt < 8; nt++)
#pragma unroll
            for (int q = 0; q < 4; q++) Cc[mt][nt][q] = 0.f;

    for (int k0 = 0; k0 < K; k0 += 64) {
        // prefetch 32 k-elements per thread per array
        float4 a4[8];
        uint4 bh[4], bl[4];
#pragma unroll
        for (int q = 0; q < 8; q++)
            a4[q] = *(const float4*)(Ap + k0 + q * 4);
#pragma unroll
        for (int q = 0; q < 4; q++) {
            bh[q] = *(const uint4*)(Bhp + k0 + q * 8);  // 8 bf16 per uint4
            bl[q] = *(const uint4*)(Blp + k0 + q * 8);
        }
        __syncthreads();
        // stage A hi/lo
#pragma unroll
        for (int q = 0; q < 8; q++) {
            uint32_t h0, l0, h1, l1;
            split2(a4[q].x, a4[q].y, h0, l0);
            split2(a4[q].z, a4[q].w, h1, l1);
            int base = la_row * TS + la_col + q * 4;
            *(uint32_t*)&sm[SA_HI + base] = h0;
            *(uint32_t*)&sm[SA_HI + base + 2] = h1;
            *(uint32_t*)&sm[SA_LO + base] = l0;
            *(uint32_t*)&sm[SA_LO + base + 2] = l1;
        }
        // stage B hi/lo
#pragma unroll
        for (int q = 0; q < 4; q++) {
            int base = la_row * TS + la_col + q * 8;
            *(uint4*)&sm[SB_HI + base] = bh[q];
            *(uint4*)&sm[SB_LO + base] = bl[q];
        }
        __syncthreads();

#pragma unroll
        for (int kc = 0; kc < 4; kc++) {
            int kk = kc * 16 + 2 * t4;
            uint32_t Ahi[2][4], Alo[2][4];
#pragma unroll
            for (int mt = 0; mt < 2; mt++) {
                int r0 = mw + mt * 16 + g;
                int r1 = r0 + 8;
                Ahi[mt][0] = *(const uint32_t*)&sm[SA_HI + r0 * TS + kk];
                Ahi[mt][1] = *(const uint32_t*)&sm[SA_HI + r1 * TS + kk];
                Ahi[mt][2] = *(const uint32_t*)&sm[SA_HI + r0 * TS + kk + 8];
                Ahi[mt][3] = *(const uint32_t*)&sm[SA_HI + r1 * TS + kk + 8];
                Alo[mt][0] = *(const uint32_t*)&sm[SA_LO + r0 * TS + kk];
                Alo[mt][1] = *(const uint32_t*)&sm[SA_LO + r1 * TS + kk];
                Alo[mt][2] = *(const uint32_t*)&sm[SA_LO + r0 * TS + kk + 8];
                Alo[mt][3] = *(const uint32_t*)&sm[SA_LO + r1 * TS + kk + 8];
            }
#pragma unroll
            for (int nt = 0; nt < 8; nt++) {
                int nrow = nw + nt * 8 + g;
                uint32_t bh0 = *(const uint32_t*)&sm[SB_HI + nrow * TS + kk];
                uint32_t bh1 = *(const uint32_t*)&sm[SB_HI + nrow * TS + kk + 8];
                uint32_t bl0 = *(const uint32_t*)&sm[SB_LO + nrow * TS + kk];
                uint32_t bl1 = *(const uint32_t*)&sm[SB_LO + nrow * TS + kk + 8];
                mma16816(Cc[0][nt], Ahi[0], bh0, bh1);
                mma16816(Cc[1][nt], Ahi[1], bh0, bh1);
                mma16816(Cc[0][nt], Ahi[0], bl0, bl1);
                mma16816(Cc[1][nt], Ahi[1], bl0, bl1);
                mma16816(Cc[0][nt], Alo[0], bh0, bh1);
                mma16816(Cc[1][nt], Alo[1], bh0, bh1);
            }
        }
    }

    // epilogue: write f32
#pragma unroll
    for (int mt = 0; mt < 2; mt++) {
        int r0 = m0 + mw + mt * 16 + g;
        int r1 = r0 + 8;
#pragma unroll
        for (int nt = 0; nt < 8; nt++) {
            int col = n0 + nw + nt * 8 + 2 * t4;
            *(float2*)(C + r0 * N + col) = make_float2(Cc[mt][nt][0], Cc[mt][nt][1]);
            *(float2*)(C + r1 * N + col) = make_float2(Cc[mt][nt][2], Cc[mt][nt][3]);
        }
    }
}

// ===================== gather taps -> f =====================================
__global__ void gather_f_kernel(const float* __restrict__ cb0,
                                const float* __restrict__ cb1,
                                const float* __restrict__ cb2,
                                const float* __restrict__ cb3) {
    int l = blockIdx.x;
    int b = blockIdx.y;
    int m = threadIdx.x;
    int br = m >> 6;
    int c = m & 63;
    int k, pad, base;
    const float* cb;
    if (br == 0)      { k = 1; base = 0; cb = cb0; }
    else if (br == 1) { k = 3; base = 1; cb = cb1; }
    else if (br == 2) { k = 5; base = 4; cb = cb2; }
    else              { k = 7; base = 9; cb = cb3; }
    pad = (k - 1) >> 1;
    float sum = cb[c];
    for (int t = 0; t < k; t++) {
        int l2 = l - pad + t;
        if ((unsigned)l2 < (unsigned)LL)
            sum += g_G[(l2 * BB + b) * GCOLS + (base + t) * 64 + c];
    }
    g_f[(l * BB + b) * MM + m] = lrelu(sum);
}

// ===================== pair kernel (mma.sync) ===============================
// grid (16, 16): blockIdx.x -> j-tile of 8, blockIdx.y -> b. 128 threads.
// Warp w handles i-rows [w*32, w*32+32) as 2 m-tiles of 16.
#define PW_STRIDE 72
#define PV_STRIDE 132
#define P_W(l)   ((l) * 18432)
#define P_WLO(l) ((l) * 18432 + 9216)
#define P_V    55296
#define P_U    89088
#define P_B    91136
#define P_RED  92160
#define P_SR   93184
#define P_TR   95232
#define PAIR_SMEM_BYTES 97280

__global__ void __launch_bounds__(128, 2)
pair_mma_kernel(const float* __restrict__ uv,
                const float* __restrict__ mw1, const float* __restrict__ mw2,
                const float* __restrict__ mw3,
                const float* __restrict__ mb0, const float* __restrict__ mb1,
                const float* __restrict__ mb2, const float* __restrict__ mb3,
                const float* __restrict__ lw0, const float* __restrict__ lb0,
                const float* __restrict__ lw1, const float* __restrict__ lb1,
                float* __restrict__ out) {
    extern __shared__ char smp[];
    int tid = threadIdx.x, w = tid >> 5, lane = tid & 31;
    int g = lane >> 2, t4 = lane & 3;
    int b = blockIdx.y, j0 = blockIdx.x * 8;

    // ---- stage weights hi/lo bf16 [n][k] stride 72 ----
    for (int l = 0; l < 3; l++) {
        const float* wsrc = (l == 0) ? mw1 : (l == 1) ? mw2 : mw3;
        __nv_bfloat16* whi = (__nv_bfloat16*)(smp + P_W(l));
        __nv_bfloat16* wlo = (__nv_bfloat16*)(smp + P_WLO(l));
        for (int idx = tid; idx < 4096; idx += 128) {
            int n = idx >> 6, k = idx & 63;
            float v = wsrc[idx];
            __nv_bfloat16 h = __float2bfloat16(v);
            __nv_bfloat16 lo = __float2bfloat16(v - __bfloat162float(h));
            whi[n * PW_STRIDE + k] = h;
            wlo[n * PW_STRIDE + k] = lo;
        }
    }
    // ---- stage V[k][i] (f32, stride 132) ----
    {
        float* V = (float*)(smp + P_V);
        const float* vp = uv + (tid * BB + b) * 128 + 64;
#pragma unroll
        for (int q = 0; q < 16; q++) {
            float4 v4 = *(const float4*)(vp + q * 4);
            V[(q * 4 + 0) * PV_STRIDE + tid] = v4.x;
            V[(q * 4 + 1) * PV_STRIDE + tid] = v4.y;
            V[(q * 4 + 2) * PV_STRIDE + tid] = v4.z;
            V[(q * 4 + 3) * PV_STRIDE + tid] = v4.w;
        }
    }
    if (tid < 64) {
        float* U = (float*)(smp + P_U);
#pragma unroll
        for (int jt = 0; jt < 8; jt++)
            U[jt * 64 + tid] = uv[((j0 + jt) * BB + b) * 128 + tid];
        float* Bs = (float*)(smp + P_B);
        Bs[tid] = mb0[tid];
        Bs[64 + tid] = mb1[tid];
        Bs[128 + tid] = mb2[tid];
        Bs[192 + tid] = mb3[tid];
    }
    __syncthreads();

    const float* V = (const float*)(smp + P_V);
    const float* U = (const float*)(smp + P_U);
    const float* BIAS = (const float*)(smp + P_B);
    float* RED = (float*)(smp + P_RED);
    float* SR = (float*)(smp + P_SR);

    for (int jt = 0; jt < 8; jt++) {
        uint32_t Ahi[2][4][4], Alo[2][4][4];

        // ---- layer-1 A fragments: x = lrelu(u + v + b0) ----
#pragma unroll
        for (int mt = 0; mt < 2; mt++) {
            int r0 = w * 32 + mt * 16 + g;
            int r1 = r0 + 8;
#pragma unroll
            for (int kc = 0; kc < 4; kc++) {
                int k0 = kc * 16 + 2 * t4;
                float ub0 = U[jt * 64 + k0]     + BIAS[k0];
                float ub1 = U[jt * 64 + k0 + 1] + BIAS[k0 + 1];
                float ub8 = U[jt * 64 + k0 + 8] + BIAS[k0 + 8];
                float ub9 = U[jt * 64 + k0 + 9] + BIAS[k0 + 9];
                float x00 = lrelu(ub0 + V[k0 * PV_STRIDE + r0]);
                float x01 = lrelu(ub1 + V[(k0 + 1) * PV_STRIDE + r0]);
                float x10 = lrelu(ub0 + V[k0 * PV_STRIDE + r1]);
                float x11 = lrelu(ub1 + V[(k0 + 1) * PV_STRIDE + r1]);
                float x08 = lrelu(ub8 + V[(k0 + 8) * PV_STRIDE + r0]);
                float x09 = lrelu(ub9 + V[(k0 + 9) * PV_STRIDE + r0]);
                float x18 = lrelu(ub8 + V[(k0 + 8) * PV_STRIDE + r1]);
                float x19 = lrelu(ub9 + V[(k0 + 9) * PV_STRIDE + r1]);
                split2(x00, x01, Ahi[mt][kc][0], Alo[mt][kc][0]);
                split2(x10, x11, Ahi[mt][kc][1], Alo[mt][kc][1]);
                split2(x08, x09, Ahi[mt][kc][2], Alo[mt][kc][2]);
                split2(x18, x19, Ahi[mt][kc][3], Alo[mt][kc][3]);
            }
        }

        // ---- 3 chained MMA layers ----
        float Cc[2][8][4];
#pragma unroll
        for (int l = 0; l < 3; l++) {
#pragma unroll
            for (int mt = 0; mt < 2; mt++)
#pragma unroll
                for (int nt = 0; nt < 8; nt++)
#pragma unroll
                    for (int q = 0; q < 4; q++) Cc[mt][nt][q] = 0.f;

            const __nv_bfloat16* whi = (const __nv_bfloat16*)(smp + P_W(l));
            const __nv_bfloat16* wlo = (const __nv_bfloat16*)(smp + P_WLO(l));
#pragma unroll
            for (int kc = 0; kc < 4; kc++) {
                int kk = kc * 16 + 2 * t4;
#pragma unroll
                for (int nt = 0; nt < 8; nt++) {
                    int nrow = nt * 8 + g;
                    uint32_t bh0 = *(const uint32_t*)&whi[nrow * PW_STRIDE + kk];
                    uint32_t bh1 = *(const uint32_t*)&whi[nrow * PW_STRIDE + kk + 8];
                    uint32_t bl0 = *(const uint32_t*)&wlo[nrow * PW_STRIDE + kk];
                    uint32_t bl1 = *(const uint32_t*)&wlo[nrow * PW_STRIDE + kk + 8];
                    mma16816(Cc[0][nt], Ahi[0][kc], bh0, bh1);
                    mma16816(Cc[1][nt], Ahi[1][kc], bh0, bh1);
                    mma16816(Cc[0][nt], Ahi[0][kc], bl0, bl1);
                    mma16816(Cc[1][nt], Ahi[1][kc], bl0, bl1);
                    mma16816(Cc[0][nt], Alo[0][kc], bh0, bh1);
                    mma16816(Cc[1][nt], Alo[1][kc], bh0, bh1);
                }
            }

            if (l < 2) {
                const float* bl = BIAS + 64 * (l + 1);
#pragma unroll
                for (int nt = 0; nt < 8; nt++) {
                    int col = nt * 8 + 2 * t4;
                    float bx = bl[col], by = bl[col + 1];
                    int kc2 = nt >> 1, ri = (nt & 1) * 2;
#pragma unroll
                    for (int mt = 0; mt < 2; mt++) {
                        float h0 = lrelu(Cc[mt][nt][0] + bx);
                        float h1 = lrelu(Cc[mt][nt][1] + by);
                        float h2 = lrelu(Cc[mt][nt][2] + bx);
                        float h3 = lrelu(Cc[mt][nt][3] + by);
                        split2(h0, h1, Ahi[mt][kc2][ri], Alo[mt][kc2][ri]);
                        split2(h2, h3, Ahi[mt][kc2][ri + 1], Alo[mt][kc2][ri + 1]);
                    }
                }
            }
        }

        // ---- final: bias + lrelu, reduce over i ----
        {
            const float* bl = BIAS + 192;
#pragma unroll
            for (int nt = 0; nt < 8; nt++) {
                int col = nt * 8 + 2 * t4;
                float bx = bl[col], by = bl[col + 1];
                float s0 = lrelu(Cc[0][nt][0] + bx) + lrelu(Cc[0][nt][2] + bx) +
                           lrelu(Cc[1][nt][0] + bx) + lrelu(Cc[1][nt][2] + bx);
                float s1 = lrelu(Cc[0][nt][1] + by) + lrelu(Cc[0][nt][3] + by) +
                           lrelu(Cc[1][nt][1] + by) + lrelu(Cc[1][nt][3] + by);
                s0 += __shfl_xor_sync(0xffffffffu, s0, 4);
                s0 += __shfl_xor_sync(0xffffffffu, s0, 8);
                s0 += __shfl_xor_sync(0xffffffffu, s0, 16);
                s1 += __shfl_xor_sync(0xffffffffu, s1, 4);
                s1 += __shfl_xor_sync(0xffffffffu, s1, 8);
                s1 += __shfl_xor_sync(0xffffffffu, s1, 16);
                if (lane < 4) {
                    RED[w * 64 + col] = s0;
                    RED[w * 64 + col + 1] = s1;
                }
            }
        }
        __syncthreads();
        if (tid < 64) {
            float s = RED[tid] + RED[64 + tid] + RED[128 + tid] + RED[192 + tid];
            SR[jt * 64 + tid] = s;
        }
        __syncthreads();
    }

    // ---- fused head: t = lrelu(s@lw0.T+lb0); out = lrelu(t@lw1.T+lb1) ----
    float* TR = (float*)(smp + P_TR);
#pragma unroll
    for (int q = 0; q < 4; q++) {
        int idx = tid + 128 * q;
        int jt = idx >> 6, o = idx & 63;
        const float* wr = lw0 + o * 64;
        float acc = lb0[o];
#pragma unroll
        for (int c = 0; c < 64; c += 4) {
            float4 w4 = *(const float4*)(wr + c);
            acc += SR[jt * 64 + c] * w4.x + SR[jt * 64 + c + 1] * w4.y +
                   SR[jt * 64 + c + 2] * w4.z + SR[jt * 64 + c + 3] * w4.w;
        }
        TR[idx] = lrelu(acc);
    }
    __syncthreads();
#pragma unroll
    for (int q = 0; q < 16; q++) {
        int idx = tid + 128 * q;
        int jt = idx >> 8, o = idx & 255;
        const float* wr = lw1 + o * 64;
        float acc = lb1[o];
#pragma unroll
        for (int c = 0; c < 64; c += 4) {
            float4 w4 = *(const float4*)(wr + c);
            acc += TR[jt * 64 + c] * w4.x + TR[jt * 64 + c + 1] * w4.y +
                   TR[jt * 64 + c + 2] * w4.z + TR[jt * 64 + c + 3] * w4.w;
        }
        out[((j0 + jt) * BB + b) * 256 + o] = lrelu(acc);
    }
}

// ===================== host launch ==========================================
extern "C" void kernel_launch(void* const* d_in, const int* in_sizes, int n_in,
                              void* d_out, int out_size) {
    const float* x   = (const float*)d_in[0];
    const float* cw0 = (const float*)d_in[1];
    const float* cb0 = (const float*)d_in[2];
    const float* cw1 = (const float*)d_in[3];
    const float* cb1 = (const float*)d_in[4];
    const float* cw2 = (const float*)d_in[5];
    const float* cb2 = (const float*)d_in[6];
    const float* cw3 = (const float*)d_in[7];
    const float* cb3 = (const float*)d_in[8];
    const float* mw0 = (const float*)d_in[9];
    const float* mb0 = (const float*)d_in[10];
    const float* mw1 = (const float*)d_in[11];
    const float* mb1 = (const float*)d_in[12];
    const float* mw2 = (const float*)d_in[13];
    const float* mb2 = (const float*)d_in[14];
    const float* mw3 = (const float*)d_in[15];
    const float* mb3 = (const float*)d_in[16];
    const float* lw0 = (const float*)d_in[17];
    const float* lb0 = (const float*)d_in[18];
    const float* lw1 = (const float*)d_in[19];
    const float* lb1 = (const float*)d_in[20];
    float* out = (float*)d_out;

    float *G, *f, *uvb;
    __nv_bfloat16 *Wrh, *Wrl, *Wuvh, *Wuvl;
    cudaGetSymbolAddress((void**)&G, g_G);
    cudaGetSymbolAddress((void**)&f, g_f);
    cudaGetSymbolAddress((void**)&uvb, g_uv);
    cudaGetSymbolAddress((void**)&Wrh, g_Wrh);
    cudaGetSymbolAddress((void**)&Wrl, g_Wrl);
    cudaGetSymbolAddress((void**)&Wuvh, g_Wuvh);
    cudaGetSymbolAddress((void**)&Wuvl, g_Wuvl);

    repack_wr_kernel<<<(EE * GCOLS + 255) / 256, 256>>>(cw0, cw1, cw2, cw3);
    pack_wuv_kernel<<<(128 * MM + 255) / 256, 256>>>(mw0);

    cudaFuncSetAttribute(gemm_tc_kernel,
                         cudaFuncAttributeMaxDynamicSharedMemorySize,
                         GEMM_SMEM_BYTES);

    // conv as GEMM: G(2048x1024) = x(2048x512) @ Wr
    gemm_tc_kernel<<<dim3(GCOLS / 128, ROWS / 128), 256, GEMM_SMEM_BYTES>>>(
        x, Wrh, Wrl, G, ROWS, GCOLS, EE);

    gather_f_kernel<<<dim3(LL, BB), 256>>>(cb0, cb1, cb2, cb3);

    // uv(2048x128) = f(2048x256) @ Wuv
    gemm_tc_kernel<<<dim3(1, ROWS / 128), 256, GEMM_SMEM_BYTES>>>(
        f, Wuvh, Wuvl, uvb, ROWS, 128, MM);

    // pair stage + fused head (mma.sync bf16 split)
    cudaFuncSetAttribute(pair_mma_kernel,
                         cudaFuncAttributeMaxDynamicSharedMemorySize,
                         PAIR_SMEM_BYTES);
    pair_mma_kernel<<<dim3(16, 16), 128, PAIR_SMEM_BYTES>>>(
        uvb, mw1, mw2, mw3, mb0, mb1, mb2, mb3,
        lw0, lb0, lw1, lb1, out);
}

// round 6
// speedup vs baseline: 2.9117x; 1.0435x over previous
#include <cuda_runtime.h>
#include <cuda_bf16.h>
#include <cstdint>

// ---------------------------------------------------------------------------
// RelationLayer: L=128, B=16, E=512, C=64, KERNELS={1,3,5,7}, M=256, OUT=256
//  1) prep: split x -> bf16 hi/lo, repack conv weights, pack Wuv  (1 launch)
//  2) G = x(2048x512) @ Wr               (tensor-core bf16-split GEMM)
//  3) f = lrelu(gather taps + bias) -> bf16 hi/lo planes
//  4) uv = f(2048x256) @ Wuv(256x128)    (tensor-core bf16-split GEMM)
//  5) pair kernel: mma.sync m16n8k16 bf16 hi/lo split, packed uint4 weight
//     fragments, in-register layer chaining, i-reduction, fused head.
// ---------------------------------------------------------------------------

#define LL 128
#define BB 16
#define EE 512
#define MM 256
#define ROWS 2048
#define GCOLS 1024

#define NX (ROWS * EE)        // 1048576
#define NW (EE * GCOLS)       // 524288
#define NU (128 * MM)         // 32768
#define NF (ROWS * MM)        // 524288

__device__ float g_G[ROWS * GCOLS];
__device__ float g_uv[ROWS * 128];
__device__ __nv_bfloat16 g_xh[NX];
__device__ __nv_bfloat16 g_xl[NX];
__device__ __nv_bfloat16 g_fh[NF];
__device__ __nv_bfloat16 g_fl[NF];
__device__ __nv_bfloat16 g_Wrh[NW];
__device__ __nv_bfloat16 g_Wrl[NW];
__device__ __nv_bfloat16 g_Wuvh[NU];
__device__ __nv_bfloat16 g_Wuvl[NU];

// ===================== helpers ==============================================
__device__ __forceinline__ float lrelu(float x) { return fmaxf(x, 0.1f * x); }

// split two f32 into bf16-hi word and bf16-lo (residual) word
// low 16 bits = first element (smaller index)
__device__ __forceinline__ void split2(float x0, float x1,
                                       uint32_t& hiw, uint32_t& low) {
    __nv_bfloat16 h0 = __float2bfloat16(x0);
    __nv_bfloat16 h1 = __float2bfloat16(x1);
    float r0 = x0 - __bfloat162float(h0);
    float r1 = x1 - __bfloat162float(h1);
    __nv_bfloat16 l0 = __float2bfloat16(r0);
    __nv_bfloat16 l1 = __float2bfloat16(r1);
    __nv_bfloat162 hp; hp.x = h0; hp.y = h1;
    __nv_bfloat162 lp; lp.x = l0; lp.y = l1;
    hiw = *(uint32_t*)&hp;
    low = *(uint32_t*)&lp;
}

__device__ __forceinline__ void split1(float v, __nv_bfloat16& h, __nv_bfloat16& l) {
    h = __float2bfloat16(v);
    l = __float2bfloat16(v - __bfloat162float(h));
}

// mma.sync m16n8k16 bf16 -> f32 accumulate (baseline PTX, no 'a' feature)
__device__ __forceinline__ void mma16816(float c[4], const uint32_t a[4],
                                         uint32_t b0, uint32_t b1) {
    asm volatile(
        "mma.sync.aligned.m16n8k16.row.col.f32.bf16.bf16.f32 "
        "{%0,%1,%2,%3}, {%4,%5,%6,%7}, {%8,%9}, {%0,%1,%2,%3};"
        : "+f"(c[0]), "+f"(c[1]), "+f"(c[2]), "+f"(c[3])
        : "r"(a[0]), "r"(a[1]), "r"(a[2]), "r"(a[3]), "r"(b0), "r"(b1));
}

// ===================== prep: splitx + repack_wr + pack_wuv ==================
__global__ void prep_kernel(const float* __restrict__ x,
                            const float* __restrict__ cw0,
                            const float* __restrict__ cw1,
                            const float* __restrict__ cw2,
                            const float* __restrict__ cw3,
                            const float* __restrict__ mw0) {
    int idx = blockIdx.x * 256 + threadIdx.x;
    if (idx < NX) {
        split1(x[idx], g_xh[idx], g_xl[idx]);
    } else if (idx < NX + NW) {
        int j = idx - NX;
        int col = j >> 9;            // n: 0..1023
        int e = j & 511;             // k
        int p = col >> 6;
        int c = col & 63;
        const float* w; int k, t;
        if (p < 1)      { w = cw0; k = 1; t = p; }
        else if (p < 4) { w = cw1; k = 3; t = p - 1; }
        else if (p < 9) { w = cw2; k = 5; t = p - 4; }
        else            { w = cw3; k = 7; t = p - 9; }
        split1(w[(c * k + t) * EE + e], g_Wrh[j], g_Wrl[j]);
    } else if (idx < NX + NW + NU) {
        int j = idx - NX - NW;
        int n = j >> 8;              // 0..127
        int k = j & 255;
        float v;
        if (n < 64) v = mw0[n * 512 + k];
        else        v = mw0[(n - 64) * 512 + 256 + k];
        split1(v, g_Wuvh[j], g_Wuvl[j]);
    }
}

// ===================== tensor-core bf16-split GEMM ==========================
// C(MxN) = A(MxK) @ B(KxN), A and B given as bf16 hi/lo planes [rows][K].
// Block tile 128x128, K-step 64, 256 threads (8 warps, each 32m x 64n).
// M%128==0, N%128==0, K%64==0.
#define TS 72            // padded k-stride in bf16 units
#define SA_HI 0
#define SA_LO (128 * TS)
#define SB_HI (256 * TS)
#define SB_LO (384 * TS)
#define GEMM_SMEM_BYTES (512 * TS * 2)

__global__ void __launch_bounds__(256, 1)
gemm_bf_kernel(const __nv_bfloat16* __restrict__ Ahig,
               const __nv_bfloat16* __restrict__ Alog,
               const __nv_bfloat16* __restrict__ Bhig,
               const __nv_bfloat16* __restrict__ Blog,
               float* __restrict__ C, int M, int N, int K) {
    extern __shared__ __nv_bfloat16 sm[];
    int tid = threadIdx.x, w = tid >> 5, lane = tid & 31;
    int g = lane >> 2, t4 = lane & 3;
    int m0 = blockIdx.y * 128, n0 = blockIdx.x * 128;
    int mw = (w & 3) * 32;          // warp m offset within tile
    int nw = (w >> 2) * 64;         // warp n offset within tile

    // loader indices: each thread covers 32 consecutive k of one row
    int la_row = tid >> 1;                    // 0..127
    int la_col = (tid & 1) * 32;              // 0 or 32
    const __nv_bfloat16* Ahp = Ahig + (m0 + la_row) * K + la_col;
    const __nv_bfloat16* Alp = Alog + (m0 + la_row) * K + la_col;
    const __nv_bfloat16* Bhp = Bhig + (n0 + la_row) * K + la_col;
    const __nv_bfloat16* Blp = Blog + (n0 + la_row) * K + la_col;

    float Cc[2][8][4];
#pragma unroll
    for (int mt = 0; mt < 2; mt++)
#pragma unroll
        for (int nt = 0; nt < 8; nt++)
#pragma unroll
            for (int q = 0; q < 4; q++) Cc[mt][nt][q] = 0.f;

    for (int k0 = 0; k0 < K; k0 += 64) {
        uint4 ah[4], al[4], bh[4], bl[4];
#pragma unroll
        for (int q = 0; q < 4; q++) {
            ah[q] = *(const uint4*)(Ahp + k0 + q * 8);  // 8 bf16 per uint4
            al[q] = *(const uint4*)(Alp + k0 + q * 8);
            bh[q] = *(const uint4*)(Bhp + k0 + q * 8);
            bl[q] = *(const uint4*)(Blp + k0 + q * 8);
        }
        __syncthreads();
#pragma unroll
        for (int q = 0; q < 4; q++) {
            int base = la_row * TS + la_col + q * 8;
            *(uint4*)&sm[SA_HI + base] = ah[q];
            *(uint4*)&sm[SA_LO + base] = al[q];
            *(uint4*)&sm[SB_HI + base] = bh[q];
            *(uint4*)&sm[SB_LO + base] = bl[q];
        }
        __syncthreads();

#pragma unroll
        for (int kc = 0; kc < 4; kc++) {
            int kk = kc * 16 + 2 * t4;
            uint32_t Ahi[2][4], Alo[2][4];
#pragma unroll
            for (int mt = 0; mt < 2; mt++) {
                int r0 = mw + mt * 16 + g;
                int r1 = r0 + 8;
                Ahi[mt][0] = *(const uint32_t*)&sm[SA_HI + r0 * TS + kk];
                Ahi[mt][1] = *(const uint32_t*)&sm[SA_HI + r1 * TS + kk];
                Ahi[mt][2] = *(const uint32_t*)&sm[SA_HI + r0 * TS + kk + 8];
                Ahi[mt][3] = *(const uint32_t*)&sm[SA_HI + r1 * TS + kk + 8];
                Alo[mt][0] = *(const uint32_t*)&sm[SA_LO + r0 * TS + kk];
                Alo[mt][1] = *(const uint32_t*)&sm[SA_LO + r1 * TS + kk];
                Alo[mt][2] = *(const uint32_t*)&sm[SA_LO + r0 * TS + kk + 8];
                Alo[mt][3] = *(const uint32_t*)&sm[SA_LO + r1 * TS + kk + 8];
            }
#pragma unroll
            for (int nt = 0; nt < 8; nt++) {
                int nrow = nw + nt * 8 + g;
                uint32_t bh0 = *(const uint32_t*)&sm[SB_HI + nrow * TS + kk];
                uint32_t bh1 = *(const uint32_t*)&sm[SB_HI + nrow * TS + kk + 8];
                uint32_t bl0 = *(const uint32_t*)&sm[SB_LO + nrow * TS + kk];
                uint32_t bl1 = *(const uint32_t*)&sm[SB_LO + nrow * TS + kk + 8];
                mma16816(Cc[0][nt], Ahi[0], bh0, bh1);
                mma16816(Cc[1][nt], Ahi[1], bh0, bh1);
                mma16816(Cc[0][nt], Ahi[0], bl0, bl1);
                mma16816(Cc[1][nt], Ahi[1], bl0, bl1);
                mma16816(Cc[0][nt], Alo[0], bh0, bh1);
                mma16816(Cc[1][nt], Alo[1], bh0, bh1);
            }
        }
    }

    // epilogue: write f32
#pragma unroll
    for (int mt = 0; mt < 2; mt++) {
        int r0 = m0 + mw + mt * 16 + g;
        int r1 = r0 + 8;
#pragma unroll
        for (int nt = 0; nt < 8; nt++) {
            int col = n0 + nw + nt * 8 + 2 * t4;
            *(float2*)(C + r0 * N + col) = make_float2(Cc[mt][nt][0], Cc[mt][nt][1]);
            *(float2*)(C + r1 * N + col) = make_float2(Cc[mt][nt][2], Cc[mt][nt][3]);
        }
    }
}

// ===================== gather taps -> f (bf16 hi/lo, ILP 8) =================
__global__ void gather_f_kernel(const float* __restrict__ cb0,
                                const float* __restrict__ cb1,
                                const float* __restrict__ cb2,
                                const float* __restrict__ cb3) {
    int t0 = blockIdx.x * 256 + threadIdx.x;   // 0..65535
#pragma unroll
    for (int q = 0; q < 8; q++) {
        int idx = t0 + q * 65536;
        int row = idx >> 8;        // (l,b): 0..2047
        int m = idx & 255;
        int l = row >> 4, b = row & 15;
        int br = m >> 6, c = m & 63;
        int k, pad, base;
        const float* cb;
        if (br == 0)      { k = 1; base = 0; cb = cb0; }
        else if (br == 1) { k = 3; base = 1; cb = cb1; }
        else if (br == 2) { k = 5; base = 4; cb = cb2; }
        else              { k = 7; base = 9; cb = cb3; }
        pad = (k - 1) >> 1;
        float sum = cb[c];
        for (int tt = 0; tt < k; tt++) {
            int l2 = l - pad + tt;
            if ((unsigned)l2 < (unsigned)LL)
                sum += g_G[(l2 * BB + b) * GCOLS + (base + tt) * 64 + c];
        }
        split1(lrelu(sum), g_fh[idx], g_fl[idx]);
    }
}

// ===================== pair kernel (mma.sync) ===============================
// grid (16, 16): blockIdx.x -> j-tile of 8, blockIdx.y -> b. 128 threads.
// Warp w handles i-rows [w*32, w*32+32) as 2 m-tiles of 16.
// Weights staged as packed uint4 fragments:
//   W4[l][kc][n][t4] = {hi_b0, hi_b1, lo_b0, lo_b1} (16B per entry)
//   index = ((l*4 + kc)*64 + n)*4 + t4;  size = 3*4*64*4*16 = 49152 B
#define PV_STRIDE 132
#define P_W4   0
#define P_V    49152
#define P_U    82944
#define P_B    84992
#define P_RED  86016
#define P_SR   87040
#define P_TR   89088
#define PAIR_SMEM_BYTES 91136

__global__ void __launch_bounds__(128, 2)
pair_mma_kernel(const float* __restrict__ uv,
                const float* __restrict__ mw1, const float* __restrict__ mw2,
                const float* __restrict__ mw3,
                const float* __restrict__ mb0, const float* __restrict__ mb1,
                const float* __restrict__ mb2, const float* __restrict__ mb3,
                const float* __restrict__ lw0, const float* __restrict__ lb0,
                const float* __restrict__ lw1, const float* __restrict__ lb1,
                float* __restrict__ out) {
    extern __shared__ char smp[];
    int tid = threadIdx.x, w = tid >> 5, lane = tid & 31;
    int g = lane >> 2, t4 = lane & 3;
    int b = blockIdx.y, j0 = blockIdx.x * 8;

    // ---- stage weights as packed uint4 fragments ----
    {
        uint4* W4 = (uint4*)(smp + P_W4);
        for (int e = tid; e < 3072; e += 128) {
            int t4i = e & 3;
            int n = (e >> 2) & 63;
            int kc = (e >> 8) & 3;
            int l = e >> 10;
            const float* wsrc = (l == 0) ? mw1 : (l == 1) ? mw2 : mw3;
            int k0 = kc * 16 + 2 * t4i;
            float2 v01 = *(const float2*)(wsrc + n * 64 + k0);
            float2 v89 = *(const float2*)(wsrc + n * 64 + k0 + 8);
            uint32_t h0, l0, h1, l1;
            split2(v01.x, v01.y, h0, l0);
            split2(v89.x, v89.y, h1, l1);
            uint4 pk; pk.x = h0; pk.y = h1; pk.z = l0; pk.w = l1;
            W4[e] = pk;
        }
    }
    // ---- stage V[k][i] (f32, stride 132) ----
    {
        float* V = (float*)(smp + P_V);
        const float* vp = uv + (tid * BB + b) * 128 + 64;
#pragma unroll
        for (int q = 0; q < 16; q++) {
            float4 v4 = *(const float4*)(vp + q * 4);
            V[(q * 4 + 0) * PV_STRIDE + tid] = v4.x;
            V[(q * 4 + 1) * PV_STRIDE + tid] = v4.y;
            V[(q * 4 + 2) * PV_STRIDE + tid] = v4.z;
            V[(q * 4 + 3) * PV_STRIDE + tid] = v4.w;
        }
    }
    if (tid < 64) {
        float* U = (float*)(smp + P_U);
#pragma unroll
        for (int jt = 0; jt < 8; jt++)
            U[jt * 64 + tid] = uv[((j0 + jt) * BB + b) * 128 + tid];
        float* Bs = (float*)(smp + P_B);
        Bs[tid] = mb0[tid];
        Bs[64 + tid] = mb1[tid];
        Bs[128 + tid] = mb2[tid];
        Bs[192 + tid] = mb3[tid];
    }
    __syncthreads();

    const float* V = (const float*)(smp + P_V);
    const float* U = (const float*)(smp + P_U);
    const float* BIAS = (const float*)(smp + P_B);
    const uint4* W4 = (const uint4*)(smp + P_W4);
    float* RED = (float*)(smp + P_RED);
    float* SR = (float*)(smp + P_SR);

    for (int jt = 0; jt < 8; jt++) {
        uint32_t Ahi[2][4][4], Alo[2][4][4];

        // ---- layer-1 A fragments: x = lrelu(u + v + b0) ----
#pragma unroll
        for (int mt = 0; mt < 2; mt++) {
            int r0 = w * 32 + mt * 16 + g;
            int r1 = r0 + 8;
#pragma unroll
            for (int kc = 0; kc < 4; kc++) {
                int k0 = kc * 16 + 2 * t4;
                float ub0 = U[jt * 64 + k0]     + BIAS[k0];
                float ub1 = U[jt * 64 + k0 + 1] + BIAS[k0 + 1];
                float ub8 = U[jt * 64 + k0 + 8] + BIAS[k0 + 8];
                float ub9 = U[jt * 64 + k0 + 9] + BIAS[k0 + 9];
                float x00 = lrelu(ub0 + V[k0 * PV_STRIDE + r0]);
                float x01 = lrelu(ub1 + V[(k0 + 1) * PV_STRIDE + r0]);
                float x10 = lrelu(ub0 + V[k0 * PV_STRIDE + r1]);
                float x11 = lrelu(ub1 + V[(k0 + 1) * PV_STRIDE + r1]);
                float x08 = lrelu(ub8 + V[(k0 + 8) * PV_STRIDE + r0]);
                float x09 = lrelu(ub9 + V[(k0 + 9) * PV_STRIDE + r0]);
                float x18 = lrelu(ub8 + V[(k0 + 8) * PV_STRIDE + r1]);
                float x19 = lrelu(ub9 + V[(k0 + 9) * PV_STRIDE + r1]);
                split2(x00, x01, Ahi[mt][kc][0], Alo[mt][kc][0]);
                split2(x10, x11, Ahi[mt][kc][1], Alo[mt][kc][1]);
                split2(x08, x09, Ahi[mt][kc][2], Alo[mt][kc][2]);
                split2(x18, x19, Ahi[mt][kc][3], Alo[mt][kc][3]);
            }
        }

        // ---- 3 chained MMA layers ----
        float Cc[2][8][4];
#pragma unroll
        for (int l = 0; l < 3; l++) {
#pragma unroll
            for (int mt = 0; mt < 2; mt++)
#pragma unroll
                for (int nt = 0; nt < 8; nt++)
#pragma unroll
                    for (int q = 0; q < 4; q++) Cc[mt][nt][q] = 0.f;

#pragma unroll
            for (int kc = 0; kc < 4; kc++) {
#pragma unroll
                for (int nt = 0; nt < 8; nt++) {
                    uint4 wq = W4[((l * 4 + kc) * 64 + nt * 8 + g) * 4 + t4];
                    mma16816(Cc[0][nt], Ahi[0][kc], wq.x, wq.y);
                    mma16816(Cc[1][nt], Ahi[1][kc], wq.x, wq.y);
                    mma16816(Cc[0][nt], Ahi[0][kc], wq.z, wq.w);
                    mma16816(Cc[1][nt], Ahi[1][kc], wq.z, wq.w);
                    mma16816(Cc[0][nt], Alo[0][kc], wq.x, wq.y);
                    mma16816(Cc[1][nt], Alo[1][kc], wq.x, wq.y);
                }
            }

            if (l < 2) {
                const float* bl = BIAS + 64 * (l + 1);
#pragma unroll
                for (int nt = 0; nt < 8; nt++) {
                    int col = nt * 8 + 2 * t4;
                    float bx = bl[col], by = bl[col + 1];
                    int kc2 = nt >> 1, ri = (nt & 1) * 2;
#pragma unroll
                    for (int mt = 0; mt < 2; mt++) {
                        float h0 = lrelu(Cc[mt][nt][0] + bx);
                        float h1 = lrelu(Cc[mt][nt][1] + by);
                        float h2 = lrelu(Cc[mt][nt][2] + bx);
                        float h3 = lrelu(Cc[mt][nt][3] + by);
                        split2(h0, h1, Ahi[mt][kc2][ri], Alo[mt][kc2][ri]);
                        split2(h2, h3, Ahi[mt][kc2][ri + 1], Alo[mt][kc2][ri + 1]);
                    }
                }
            }
        }

        // ---- final: bias + lrelu, reduce over i ----
        {
            const float* bl = BIAS + 192;
#pragma unroll
            for (int nt = 0; nt < 8; nt++) {
                int col = nt * 8 + 2 * t4;
                float bx = bl[col], by = bl[col + 1];
                float s0 = lrelu(Cc[0][nt][0] + bx) + lrelu(Cc[0][nt][2] + bx) +
                           lrelu(Cc[1][nt][0] + bx) + lrelu(Cc[1][nt][2] + bx);
                float s1 = lrelu(Cc[0][nt][1] + by) + lrelu(Cc[0][nt][3] + by) +
                           lrelu(Cc[1][nt][1] + by) + lrelu(Cc[1][nt][3] + by);
                s0 += __shfl_xor_sync(0xffffffffu, s0, 4);
                s0 += __shfl_xor_sync(0xffffffffu, s0, 8);
                s0 += __shfl_xor_sync(0xffffffffu, s0, 16);
                s1 += __shfl_xor_sync(0xffffffffu, s1, 4);
                s1 += __shfl_xor_sync(0xffffffffu, s1, 8);
                s1 += __shfl_xor_sync(0xffffffffu, s1, 16);
                if (lane < 4) {
                    RED[w * 64 + col] = s0;
                    RED[w * 64 + col + 1] = s1;
                }
            }
        }
        __syncthreads();
        if (tid < 64) {
            float s = RED[tid] + RED[64 + tid] + RED[128 + tid] + RED[192 + tid];
            SR[jt * 64 + tid] = s;
        }
        __syncthreads();
    }

    // ---- fused head: t = lrelu(s@lw0.T+lb0); out = lrelu(t@lw1.T+lb1) ----
    float* TR = (float*)(smp + P_TR);
#pragma unroll
    for (int q = 0; q < 4; q++) {
        int idx = tid + 128 * q;
        int jt = idx >> 6, o = idx & 63;
        const float* wr = lw0 + o * 64;
        float acc = lb0[o];
#pragma unroll
        for (int c = 0; c < 64; c += 4) {
            float4 w4 = *(const float4*)(wr + c);
            acc += SR[jt * 64 + c] * w4.x + SR[jt * 64 + c + 1] * w4.y +
                   SR[jt * 64 + c + 2] * w4.z + SR[jt * 64 + c + 3] * w4.w;
        }
        TR[idx] = lrelu(acc);
    }
    __syncthreads();
#pragma unroll
    for (int q = 0; q < 16; q++) {
        int idx = tid + 128 * q;
        int jt = idx >> 8, o = idx & 255;
        const float* wr = lw1 + o * 64;
        float acc = lb1[o];
#pragma unroll
        for (int c = 0; c < 64; c += 4) {
            float4 w4 = *(const float4*)(wr + c);
            acc += TR[jt * 64 + c] * w4.x + TR[jt * 64 + c + 1] * w4.y +
                   TR[jt * 64 + c + 2] * w4.z + TR[jt * 64 + c + 3] * w4.w;
        }
        out[((j0 + jt) * BB + b) * 256 + o] = lrelu(acc);
    }
}

// ===================== host launch ==========================================
extern "C" void kernel_launch(void* const* d_in, const int* in_sizes, int n_in,
                              void* d_out, int out_size) {
    const float* x   = (const float*)d_in[0];
    const float* cw0 = (const float*)d_in[1];
    const float* cb0 = (const float*)d_in[2];
    const float* cw1 = (const float*)d_in[3];
    const float* cb1 = (const float*)d_in[4];
    const float* cw2 = (const float*)d_in[5];
    const float* cb2 = (const float*)d_in[6];
    const float* cw3 = (const float*)d_in[7];
    const float* cb3 = (const float*)d_in[8];
    const float* mw0 = (const float*)d_in[9];
    const float* mb0 = (const float*)d_in[10];
    const float* mw1 = (const float*)d_in[11];
    const float* mb1 = (const float*)d_in[12];
    const float* mw2 = (const float*)d_in[13];
    const float* mb2 = (const float*)d_in[14];
    const float* mw3 = (const float*)d_in[15];
    const float* mb3 = (const float*)d_in[16];
    const float* lw0 = (const float*)d_in[17];
    const float* lb0 = (const float*)d_in[18];
    const float* lw1 = (const float*)d_in[19];
    const float* lb1 = (const float*)d_in[20];
    float* out = (float*)d_out;

    float *G, *uvb;
    __nv_bfloat16 *xh, *xl, *fh, *fl, *Wrh, *Wrl, *Wuvh, *Wuvl;
    cudaGetSymbolAddress((void**)&G, g_G);
    cudaGetSymbolAddress((void**)&uvb, g_uv);
    cudaGetSymbolAddress((void**)&xh, g_xh);
    cudaGetSymbolAddress((void**)&xl, g_xl);
    cudaGetSymbolAddress((void**)&fh, g_fh);
    cudaGetSymbolAddress((void**)&fl, g_fl);
    cudaGetSymbolAddress((void**)&Wrh, g_Wrh);
    cudaGetSymbolAddress((void**)&Wrl, g_Wrl);
    cudaGetSymbolAddress((void**)&Wuvh, g_Wuvh);
    cudaGetSymbolAddress((void**)&Wuvl, g_Wuvl);

    // 1) prep (split x, repack conv weights, pack Wuv)
    prep_kernel<<<(NX + NW + NU + 255) / 256, 256>>>(x, cw0, cw1, cw2, cw3, mw0);

    cudaFuncSetAttribute(gemm_bf_kernel,
                         cudaFuncAttributeMaxDynamicSharedMemorySize,
                         GEMM_SMEM_BYTES);

    // 2) conv as GEMM: G(2048x1024) = x(2048x512) @ Wr
    gemm_bf_kernel<<<dim3(GCOLS / 128, ROWS / 128), 256, GEMM_SMEM_BYTES>>>(
        xh, xl, Wrh, Wrl, G, ROWS, GCOLS, EE);

    // 3) gather taps -> f (bf16 hi/lo planes)
    gather_f_kernel<<<256, 256>>>(cb0, cb1, cb2, cb3);

    // 4) uv(2048x128) = f(2048x256) @ Wuv
    gemm_bf_kernel<<<dim3(1, ROWS / 128), 256, GEMM_SMEM_BYTES>>>(
        fh, fl, Wuvh, Wuvl, uvb, ROWS, 128, MM);

    // 5) pair stage + fused head (mma.sync bf16 split)
    cudaFuncSetAttribute(pair_mma_kernel,
                         cudaFuncAttributeMaxDynamicSharedMemorySize,
                         PAIR_SMEM_BYTES);
    pair_mma_kernel<<<dim3(16, 16), 128, PAIR_SMEM_BYTES>>>(
        uvb, mw1, mw2, mw3, mb0, mb1, mb2, mb3,
        lw0, lb0, lw1, lb1, out);
}